// round 8
// baseline (speedup 1.0000x reference)
#include <cuda_runtime.h>

// Problem constants (fixed by the dataset): N=50000, NIN=128, NOUT=64, H=4, C=16, E=800000
#define MAXN 50000
#define MAXE 800000
#define MAXET (MAXE + MAXN)   // edges + self-loops
#define NH   4      // heads
#define NC   16     // channels per head
#define NOUT 64     // NH*NC

// Scratch (allocation-free rule: __device__ globals)
__device__ __align__(16) float g_xw[MAXN * NOUT];    // 12.8 MB
__device__ __align__(16) float g_as[MAXN * NH];
__device__ __align__(16) float g_ad[MAXN * NH];
__device__ __align__(16) float g_den[MAXN * NH];
__device__ __align__(16) float g_alp[MAXET * NH];    // attention per edge, 13.6 MB
__device__ __align__(16) int2  g_sd[MAXET];          // packed (src,dst) int32, 6.8 MB
__device__ int g_is64;                               // edge_index dtype flag

__device__ __forceinline__ float lrelu(float v) {
    return v > 0.f ? v : 0.2f * v;
}

// Vectorized global reduction: one instruction, 16 bytes (sm_90+).
__device__ __forceinline__ void red_add_v4(float* p, float4 m) {
    asm volatile("red.global.add.v4.f32 [%0], {%1, %2, %3, %4};"
                 :: "l"(p), "f"(m.x), "f"(m.y), "f"(m.z), "f"(m.w)
                 : "memory");
}

// ---------------------------------------------------------------------------
// K0: detect edge_index element width. For little-endian int64 indices in
// [0, 2^31), every odd 32-bit word is 0. For int32 edge data, odd words are
// uniform node ids in [0, 50000) — 4096 consecutive zeros is impossible
// (P ~ 50000^-4096). Deterministic: same input -> same flag every launch.
// ---------------------------------------------------------------------------
__global__ void detect_kernel(const int* __restrict__ ei32)
{
    __shared__ int any_nonzero;
    if (threadIdx.x == 0) any_nonzero = 0;
    __syncthreads();
    for (int i = threadIdx.x; i < 4096; i += blockDim.x)
        if (ei32[2 * i + 1] != 0) any_nonzero = 1;
    __syncthreads();
    if (threadIdx.x == 0) g_is64 = (any_nonzero == 0) ? 1 : 0;
}

// ---------------------------------------------------------------------------
// K1: xw = x @ W ([n,128]@[128,64]) with fused attention-logit epilogue.
// 32 rows/block, 256 threads, K in 2 chunks of 64; thread (ty,tx) owns a
// 2-row x 4-col register tile (cols tx*4.., all within head h = tx>>2).
// Epilogue: per-head dots with att_src/att_dst via 4-lane shfl reduction
// (lanes of a (row,head) group differ by 1,2 -> same warp). Also zeroes den.
// ---------------------------------------------------------------------------
__global__ void gemm_kernel(const float* __restrict__ x,
                            const float* __restrict__ W,
                            const float* __restrict__ att_src,
                            const float* __restrict__ att_dst, int n)
{
    __shared__ float Xs[32][68];   // pad 68: no bank conflicts
    __shared__ float Ws[64][64];

    const int t  = threadIdx.x;
    const int tx = t & 15;         // col group (cols tx*4 .. tx*4+3)
    const int ty = t >> 4;         // row group (rows ty*2, ty*2+1)
    const int row0 = blockIdx.x * 32;

    float acc[2][4] = {{0.f,0.f,0.f,0.f},{0.f,0.f,0.f,0.f}};

    for (int kc = 0; kc < 128; kc += 64) {
        #pragma unroll
        for (int i = 0; i < 4; i++) {
            int idx4 = t + i * 256;            // 0..1023
            int kr = idx4 >> 4;                // 0..63
            int c4 = (idx4 & 15) << 2;         // 0,4,..,60
            *(float4*)&Ws[kr][c4] = *(const float4*)&W[(kc + kr) * NOUT + c4];
        }
        #pragma unroll
        for (int i = 0; i < 2; i++) {
            int idx4 = t + i * 256;            // 0..511
            int r  = idx4 >> 4;                // 0..31
            int c4 = (idx4 & 15) << 2;
            float4 v = make_float4(0.f, 0.f, 0.f, 0.f);
            if (row0 + r < n)
                v = *(const float4*)&x[(size_t)(row0 + r) * 128 + kc + c4];
            *(float4*)&Xs[r][c4] = v;
        }
        __syncthreads();

        #pragma unroll 16
        for (int k = 0; k < 64; k++) {
            float4 b = *(float4*)&Ws[k][tx << 2];
            float a0 = Xs[ty * 2 + 0][k];
            float a1 = Xs[ty * 2 + 1][k];
            acc[0][0] = fmaf(a0, b.x, acc[0][0]);
            acc[0][1] = fmaf(a0, b.y, acc[0][1]);
            acc[0][2] = fmaf(a0, b.z, acc[0][2]);
            acc[0][3] = fmaf(a0, b.w, acc[0][3]);
            acc[1][0] = fmaf(a1, b.x, acc[1][0]);
            acc[1][1] = fmaf(a1, b.y, acc[1][1]);
            acc[1][2] = fmaf(a1, b.z, acc[1][2]);
            acc[1][3] = fmaf(a1, b.w, acc[1][3]);
        }
        __syncthreads();
    }

    // Store xw tile
    #pragma unroll
    for (int i = 0; i < 2; i++) {
        int r = row0 + ty * 2 + i;
        if (r < n) {
            float4 v = make_float4(acc[i][0], acc[i][1], acc[i][2], acc[i][3]);
            *(float4*)&g_xw[(size_t)r * NOUT + (tx << 2)] = v;
        }
    }

    // Fused attention-logit epilogue.
    // This thread's 4 cols live in head h at channel offset (tx&3)*4.
    const int h  = tx >> 2;
    const int co = (tx & 3) << 2;
    float4 sa = __ldg((const float4*)&att_src[h * NC + co]);
    float4 da = __ldg((const float4*)&att_dst[h * NC + co]);

    #pragma unroll
    for (int i = 0; i < 2; i++) {
        float ps = acc[i][0]*sa.x + acc[i][1]*sa.y + acc[i][2]*sa.z + acc[i][3]*sa.w;
        float pd = acc[i][0]*da.x + acc[i][1]*da.y + acc[i][2]*da.z + acc[i][3]*da.w;
        // reduce over the 4 lanes with the same (row, head): lane ids differ in bits 0,1
        ps += __shfl_xor_sync(0xffffffffu, ps, 1);
        pd += __shfl_xor_sync(0xffffffffu, pd, 1);
        ps += __shfl_xor_sync(0xffffffffu, ps, 2);
        pd += __shfl_xor_sync(0xffffffffu, pd, 2);
        int r = row0 + ty * 2 + i;
        if ((tx & 3) == 0 && r < n) {
            g_as[r * NH + h]  = ps;
            g_ad[r * NH + h]  = pd;
            g_den[r * NH + h] = 0.f;
        }
    }
}

// ---------------------------------------------------------------------------
// K3: out = bias (d_out is poisoned before timing). float4-vectorized.
// ---------------------------------------------------------------------------
__global__ void init_out_kernel(float* __restrict__ out,
                                const float* __restrict__ bias, int n)
{
    int i = blockIdx.x * blockDim.x + threadIdx.x;   // over n*16 float4s
    if (i >= n * (NOUT / 4)) return;
    float4 b = __ldg((const float4*)&bias[(i & 15) << 2]);
    ((float4*)out)[i] = b;
}

// ---------------------------------------------------------------------------
// K4: per-edge unnormalized attention e = exp(lrelu(a_src[s]+a_dst[d]));
// store it + packed int32 (src,dst); accumulate the denominator.
// One thread per edge (incl. implicit self-loops at the tail).
// Handles both int64 and int32 edge_index layouts via g_is64 (uniform branch).
// Indices clamped to [0, n-1]: a no-op for valid graphs, turns any residual
// dtype surprise into a measurable rel_err instead of an IMA.
// No max-shift needed: logits are ~N(0,2), |v| < ~10, fp32-safe; alpha is
// shift-invariant so result matches the reference.
// ---------------------------------------------------------------------------
__global__ void denom_kernel(const void* __restrict__ eiv, int n, int e)
{
    int i = blockIdx.x * blockDim.x + threadIdx.x;
    int etot = e + n;
    if (i >= etot) return;
    int s, d;
    if (i < e) {
        if (g_is64) {
            const long long* ei = (const long long*)eiv;
            s = (int)__ldg(&ei[i]); d = (int)__ldg(&ei[e + i]);
        } else {
            const int* ei = (const int*)eiv;
            s = __ldg(&ei[i]); d = __ldg(&ei[e + i]);
        }
        s = min(max(s, 0), n - 1);
        d = min(max(d, 0), n - 1);
    } else {
        s = i - e; d = s;
    }
    g_sd[i] = make_int2(s, d);

    float4 as = __ldg(&((const float4*)g_as)[s]);
    float4 ad = __ldg(&((const float4*)g_ad)[d]);
    float4 ev;
    ev.x = __expf(lrelu(as.x + ad.x));
    ev.y = __expf(lrelu(as.y + ad.y));
    ev.z = __expf(lrelu(as.z + ad.z));
    ev.w = __expf(lrelu(as.w + ad.w));
    ((float4*)g_alp)[i] = ev;            // coalesced STG.128
    red_add_v4(&g_den[d * NH], ev);
}

// ---------------------------------------------------------------------------
// K4c: normalize attention in place: alp[i][h] /= (den[dst][h] + 1e-16).
// One thread per edge (float4). Fused divide (850K divides, negligible).
// ---------------------------------------------------------------------------
__global__ void norm_kernel(int etot)
{
    int i = blockIdx.x * blockDim.x + threadIdx.x;
    if (i >= etot) return;
    int d = __ldg(&g_sd[i]).y;
    float4 a = ((const float4*)g_alp)[i];
    float4 dn = __ldg(&((const float4*)g_den)[d]);
    a.x /= (dn.x + 1e-16f);
    a.y /= (dn.y + 1e-16f);
    a.z /= (dn.z + 1e-16f);
    a.w /= (dn.w + 1e-16f);
    ((float4*)g_alp)[i] = a;
}

// ---------------------------------------------------------------------------
// K5: scatter messages: out[d, c] += xw[s, c] * alpha[edge, h]
// 16 threads per edge, 4 channels (one float4) each. Minimal hot pass:
//   LDG.64 (packed sd) + LDG.32 (alpha) + LDG.128.NC (xw) + 4 FMUL + RED.128
// ---------------------------------------------------------------------------
__global__ void scatter_kernel(float* __restrict__ out, int etot)
{
    int idx = blockIdx.x * blockDim.x + threadIdx.x;  // over etot*16 (13.6M)
    if (idx >= etot * 16) return;
    int i = idx >> 4;          // edge
    int q = idx & 15;          // quad index: channels q*4 .. q*4+3
    int h = q >> 2;            // head

    int2 sd = __ldg(&g_sd[i]);
    float alpha = __ldg(&g_alp[i * NH + h]);

    float4 xw = __ldg((const float4*)&g_xw[(size_t)sd.x * NOUT + (q << 2)]);
    float4 m = make_float4(xw.x * alpha, xw.y * alpha, xw.z * alpha, xw.w * alpha);
    red_add_v4(&out[(size_t)sd.y * NOUT + (q << 2)], m);
}

// ---------------------------------------------------------------------------
extern "C" void kernel_launch(void* const* d_in, const int* in_sizes, int n_in,
                              void* d_out, int out_size)
{
    const float* x       = (const float*)d_in[0];
    const void*  ei      = d_in[1];                 // [2, E], int64 OR int32 (detected)
    // d_in[2] = edge_attr (ignored by the layer)
    const float* W       = (const float*)d_in[3];
    const float* att_src = (const float*)d_in[4];
    const float* att_dst = (const float*)d_in[5];
    const float* bias    = (const float*)d_in[6];
    float*       out     = (float*)d_out;

    int n = in_sizes[0] / 128;   // 50000
    int e = in_sizes[1] / 2;     // 800000
    int etot = e + n;

    detect_kernel<<<1, 256>>>((const int*)ei);
    gemm_kernel<<<(n + 31) / 32, 256>>>(x, W, att_src, att_dst, n);
    init_out_kernel<<<(n * (NOUT / 4) + 255) / 256, 256>>>(out, bias, n);
    denom_kernel<<<(etot + 255) / 256, 256>>>(ei, n, e);
    norm_kernel<<<(etot + 255) / 256, 256>>>(etot);
    scatter_kernel<<<(etot * 16 + 255) / 256, 256>>>(out, etot);
}